// round 1
// baseline (speedup 1.0000x reference)
#include <cuda_runtime.h>

#define C 32
#define NMAX 100000
#define EMAX 1600000
#define FULLMASK 0xffffffffu

// ---------------- device scratch (no allocations allowed) ----------------
__device__ float g_hd [NMAX * C];          // x @ (Wa1 W_dst)^T
__device__ float g_hs [NMAX * C];          // x @ (Wa1 W_src)^T
__device__ float g_v  [NMAX * C];          // x @ W_val^T
__device__ float g_den[NMAX * C];          // softmax denominators
__device__ float g_acc[NMAX * C];          // scatter-sum accumulator
__device__ float g_ex [(long long)EMAX * C]; // exp(logits) per edge
__device__ float g_Wcd[C * C];             // Wa1 @ W_dst
__device__ float g_Wcs[C * C];             // Wa1 @ W_src
__device__ float g_Wp2[C * 3];             // Wa1 @ Wp
__device__ float g_c0 [C];                 // Wa1 @ bp + ba1
__device__ double g_sum  [C];
__device__ double g_sumsq[C];
__device__ float g_gain[C];                // BN gain  (gamma * rsqrt(var+eps))
__device__ float g_b2  [C];                // BN shift (beta - mu*gain)
__device__ int   g_is64;

// ---------------- int64 vs int32 edge_index detection ----------------
__global__ void k_detect(const long long* ei, int E, int n) {
    if (threadIdx.x == 0 && blockIdx.x == 0) {
        int cnt = E < 256 ? E : 256;   // stays within first half of buffer even if int32
        int ok = 1;
        for (int i = 0; i < cnt; i++) {
            long long v = ei[i];
            if (v < 0 || v >= (long long)n) { ok = 0; break; }
        }
        g_is64 = ok;
    }
}

// ---------------- fold Wa1 into W_dst / W_src / Wp / bp ----------------
__global__ void k_fold(const float* Wsrc, const float* Wdst, const float* Wp,
                       const float* bp, const float* Wa1, const float* ba1) {
    int t = threadIdx.x;
    if (t < C * C) {
        int c = t >> 5, m = t & 31;
        float sd = 0.f, ss = 0.f;
        #pragma unroll
        for (int k = 0; k < C; k++) {
            float a = Wa1[c * C + k];
            sd = fmaf(a, Wdst[k * C + m], sd);
            ss = fmaf(a, Wsrc[k * C + m], ss);
        }
        g_Wcd[t] = sd;
        g_Wcs[t] = ss;
    }
    if (t < C * 3) {
        int c = t / 3, j = t % 3;
        float s = 0.f;
        #pragma unroll
        for (int k = 0; k < C; k++) s = fmaf(Wa1[c * C + k], Wp[k * 3 + j], s);
        g_Wp2[t] = s;
    }
    if (t < C) {
        float s = 0.f;
        #pragma unroll
        for (int k = 0; k < C; k++) s = fmaf(Wa1[t * C + k], bp[k], s);
        g_c0[t] = s + ba1[t];
        g_sum[t] = 0.0;
        g_sumsq[t] = 0.0;
    }
}

// ---------------- zero accumulators ----------------
__global__ void k_zero(int n) {
    int i = blockIdx.x * blockDim.x + threadIdx.x;
    int stride = gridDim.x * blockDim.x;
    int tot = n * C;
    for (; i < tot; i += stride) { g_den[i] = 0.f; g_acc[i] = 0.f; }
}

// ---------------- node projections: hd, hs, v ----------------
__global__ __launch_bounds__(256) void k_node(const float* x, const float* Wval, int n) {
    __shared__ float sd[C * 33], ss[C * 33], sv[C * 33];
    for (int t = threadIdx.x; t < C * C; t += blockDim.x) {
        int c = t >> 5, k = t & 31;
        sd[c * 33 + k] = g_Wcd[t];
        ss[c * 33 + k] = g_Wcs[t];
        sv[c * 33 + k] = Wval[t];
    }
    __syncthreads();
    const int lane = threadIdx.x & 31;
    const int warp = (blockIdx.x * blockDim.x + threadIdx.x) >> 5;
    const int nw   = (gridDim.x * blockDim.x) >> 5;
    for (int nd = warp; nd < n; nd += nw) {
        float xv = x[nd * C + lane];
        float ad = 0.f, as_ = 0.f, av = 0.f;
        #pragma unroll
        for (int k = 0; k < C; k++) {
            float xk = __shfl_sync(FULLMASK, xv, k);
            ad  = fmaf(sd[lane * 33 + k], xk, ad);
            as_ = fmaf(ss[lane * 33 + k], xk, as_);
            av  = fmaf(sv[lane * 33 + k], xk, av);
        }
        g_hd[nd * C + lane] = ad;
        g_hs[nd * C + lane] = as_;
        g_v [nd * C + lane] = av;
    }
}

// ---------------- pass 1 over edges: BN statistics of h ----------------
__global__ __launch_bounds__(256) void k_stats(const void* eiv, const float* pos,
                                               int n, int E) {
    const int lane = threadIdx.x & 31;
    const int warp = (blockIdx.x * blockDim.x + threadIdx.x) >> 5;
    const int nw   = (gridDim.x * blockDim.x) >> 5;
    const int is64 = g_is64;
    const long long* e64 = (const long long*)eiv;
    const int*       e32 = (const int*)eiv;
    const float wp0 = g_Wp2[lane * 3 + 0];
    const float wp1 = g_Wp2[lane * 3 + 1];
    const float wp2 = g_Wp2[lane * 3 + 2];
    const float c0v = g_c0[lane];
    float sum = 0.f, sq = 0.f;
    for (int e = warp; e < E; e += nw) {
        int src, dst;
        if (is64) { src = (int)e64[e]; dst = (int)e64[E + e]; }
        else      { src = e32[e];      dst = e32[E + e]; }
        float pd = (lane < 3) ? pos[dst * 3 + lane] : 0.f;
        float ps = (lane < 3) ? pos[src * 3 + lane] : 0.f;
        float d  = pd - ps;
        float dx = __shfl_sync(FULLMASK, d, 0);
        float dy = __shfl_sync(FULLMASK, d, 1);
        float dz = __shfl_sync(FULLMASK, d, 2);
        float h = g_hd[dst * C + lane] - g_hs[src * C + lane] + c0v;
        h = fmaf(wp0, dx, h);
        h = fmaf(wp1, dy, h);
        h = fmaf(wp2, dz, h);
        sum += h;
        sq = fmaf(h, h, sq);
    }
    atomicAdd(&g_sum[lane],   (double)sum);
    atomicAdd(&g_sumsq[lane], (double)sq);
}

// ---------------- finalize BN affine params ----------------
__global__ void k_bn(const float* gamma, const float* beta, int E) {
    int c = threadIdx.x;
    if (c < C) {
        double mu  = g_sum[c]   / (double)E;
        double var = g_sumsq[c] / (double)E - mu * mu;
        float g = gamma[c] * rsqrtf((float)var + 1e-5f);
        g_gain[c] = g;
        g_b2[c]   = beta[c] - (float)mu * g;
    }
}

// ---------------- pass 2 over edges: logits -> exp, den scatter ----------------
__global__ __launch_bounds__(256) void k_logits(const void* eiv, const float* pos,
                                                const float* Wa2, const float* ba2,
                                                int n, int E) {
    __shared__ float swa[C * 33];
    for (int t = threadIdx.x; t < C * C; t += blockDim.x)
        swa[(t >> 5) * 33 + (t & 31)] = Wa2[t];
    __syncthreads();
    const int lane = threadIdx.x & 31;
    const int warp = (blockIdx.x * blockDim.x + threadIdx.x) >> 5;
    const int nw   = (gridDim.x * blockDim.x) >> 5;
    const int is64 = g_is64;
    const long long* e64 = (const long long*)eiv;
    const int*       e32 = (const int*)eiv;
    float wa[C];
    #pragma unroll
    for (int k = 0; k < C; k++) wa[k] = swa[lane * 33 + k];
    const float wp0 = g_Wp2[lane * 3 + 0];
    const float wp1 = g_Wp2[lane * 3 + 1];
    const float wp2 = g_Wp2[lane * 3 + 2];
    const float c0v = g_c0[lane];
    const float gv  = g_gain[lane];
    const float bv  = g_b2[lane];
    const float bav = ba2[lane];
    for (int e = warp; e < E; e += nw) {
        int src, dst;
        if (is64) { src = (int)e64[e]; dst = (int)e64[E + e]; }
        else      { src = e32[e];      dst = e32[E + e]; }
        float pd = (lane < 3) ? pos[dst * 3 + lane] : 0.f;
        float ps = (lane < 3) ? pos[src * 3 + lane] : 0.f;
        float d  = pd - ps;
        float dx = __shfl_sync(FULLMASK, d, 0);
        float dy = __shfl_sync(FULLMASK, d, 1);
        float dz = __shfl_sync(FULLMASK, d, 2);
        float h = g_hd[dst * C + lane] - g_hs[src * C + lane] + c0v;
        h = fmaf(wp0, dx, h);
        h = fmaf(wp1, dy, h);
        h = fmaf(wp2, dz, h);
        float hn = fmaxf(fmaf(h, gv, bv), 0.f);   // BN + ReLU
        float acc = bav;
        #pragma unroll
        for (int k = 0; k < C; k++)
            acc = fmaf(wa[k], __shfl_sync(FULLMASK, hn, k), acc);
        float ex = __expf(acc);                   // max-free softmax numerator
        g_ex[(long long)e * C + lane] = ex;
        atomicAdd(&g_den[dst * C + lane], ex);
    }
}

// ---------------- pass 3 over edges: alpha * (v + delta) scatter ----------------
__global__ __launch_bounds__(256) void k_msg(const void* eiv, const float* pos,
                                             const float* Wp, const float* bp,
                                             int n, int E) {
    const int lane = threadIdx.x & 31;
    const int warp = (blockIdx.x * blockDim.x + threadIdx.x) >> 5;
    const int nw   = (gridDim.x * blockDim.x) >> 5;
    const int is64 = g_is64;
    const long long* e64 = (const long long*)eiv;
    const int*       e32 = (const int*)eiv;
    const float wp0 = Wp[lane * 3 + 0];
    const float wp1 = Wp[lane * 3 + 1];
    const float wp2 = Wp[lane * 3 + 2];
    const float bpv = bp[lane];
    for (int e = warp; e < E; e += nw) {
        int src, dst;
        if (is64) { src = (int)e64[e]; dst = (int)e64[E + e]; }
        else      { src = e32[e];      dst = e32[E + e]; }
        float pd = (lane < 3) ? pos[dst * 3 + lane] : 0.f;
        float ps = (lane < 3) ? pos[src * 3 + lane] : 0.f;
        float d  = pd - ps;
        float dx = __shfl_sync(FULLMASK, d, 0);
        float dy = __shfl_sync(FULLMASK, d, 1);
        float dz = __shfl_sync(FULLMASK, d, 2);
        float delta = bpv;
        delta = fmaf(wp0, dx, delta);
        delta = fmaf(wp1, dy, delta);
        delta = fmaf(wp2, dz, delta);
        float ex  = g_ex[(long long)e * C + lane];
        float den = g_den[dst * C + lane];
        float alpha = __fdividef(ex, den + 1e-16f);
        float msg = alpha * (g_v[src * C + lane] + delta);
        atomicAdd(&g_acc[dst * C + lane], msg);
    }
}

// ---------------- final: out = acc @ Wu^T + bu + x ----------------
__global__ __launch_bounds__(256) void k_out(const float* x, const float* Wu,
                                             const float* bu, float* out, int n) {
    __shared__ float sw[C * 33];
    for (int t = threadIdx.x; t < C * C; t += blockDim.x)
        sw[(t >> 5) * 33 + (t & 31)] = Wu[t];
    __syncthreads();
    const int lane = threadIdx.x & 31;
    const int warp = (blockIdx.x * blockDim.x + threadIdx.x) >> 5;
    const int nw   = (gridDim.x * blockDim.x) >> 5;
    float wr[C];
    #pragma unroll
    for (int k = 0; k < C; k++) wr[k] = sw[lane * 33 + k];
    const float buv = bu[lane];
    for (int nd = warp; nd < n; nd += nw) {
        float a = g_acc[nd * C + lane];
        float s = buv + x[nd * C + lane];
        #pragma unroll
        for (int k = 0; k < C; k++)
            s = fmaf(wr[k], __shfl_sync(FULLMASK, a, k), s);
        out[nd * C + lane] = s;
    }
}

// ---------------- launch ----------------
extern "C" void kernel_launch(void* const* d_in, const int* in_sizes, int n_in,
                              void* d_out, int out_size) {
    const float* x     = (const float*)d_in[0];
    const float* pos   = (const float*)d_in[1];
    const void*  ei    = d_in[2];
    const float* Wsrc  = (const float*)d_in[3];
    const float* Wdst  = (const float*)d_in[4];
    const float* Wval  = (const float*)d_in[5];
    const float* Wp    = (const float*)d_in[6];
    const float* bp    = (const float*)d_in[7];
    const float* Wa1   = (const float*)d_in[8];
    const float* ba1   = (const float*)d_in[9];
    const float* gamma = (const float*)d_in[10];
    const float* beta  = (const float*)d_in[11];
    const float* Wa2   = (const float*)d_in[12];
    const float* ba2   = (const float*)d_in[13];
    const float* Wu    = (const float*)d_in[14];
    const float* bu    = (const float*)d_in[15];
    float* out = (float*)d_out;

    int n = in_sizes[0] / C;
    int E = in_sizes[2] / 2;

    dim3 gb(1184), tb(256);   // 8 blocks/SM-class grid, grid-stride inside

    k_detect<<<1, 1>>>((const long long*)ei, E, n);
    k_fold  <<<1, 1024>>>(Wsrc, Wdst, Wp, bp, Wa1, ba1);
    k_zero  <<<gb, tb>>>(n);
    k_node  <<<gb, tb>>>(x, Wval, n);
    k_stats <<<gb, tb>>>(ei, pos, n, E);
    k_bn    <<<1, 32>>>(gamma, beta, E);
    k_logits<<<gb, tb>>>(ei, pos, Wa2, ba2, n, E);
    k_msg   <<<gb, tb>>>(ei, pos, Wp, bp, n, E);
    k_out   <<<gb, tb>>>(x, Wu, bu, out, n);
}

// round 2
// speedup vs baseline: 1.6348x; 1.6348x over previous
#include <cuda_runtime.h>

#define C 32
#define NMAX 100000
#define EMAX 1600000
#define FULLMASK 0xffffffffu

// ---------------- device scratch ----------------
__device__ float g_Hd [NMAX * C];   // (Wa1 Wdst)x + (Wa1 Wp)pos
__device__ float g_Hs [NMAX * C];   // (Wa1 Wsrc)x + (Wa1 Wp)pos
__device__ float g_Vs [NMAX * C];   // Wval x - Wp pos
__device__ float g_Pd [NMAX * C];   // Wp pos + bp
__device__ float g_den[NMAX * C];   // sum of ex per dst
__device__ float g_acc[NMAX * C];   // sum of ex*Vs[src] per dst
__device__ int2  g_edge[EMAX];      // packed (src,dst) int32
__device__ float g_Wcd[C * C];      // Wa1 @ W_dst
__device__ float g_Wcs[C * C];      // Wa1 @ W_src
__device__ float g_Wp2[C * 3];      // Wa1 @ Wp
__device__ float g_c0 [C];          // Wa1 @ bp + ba1
__device__ double g_sum  [C];
__device__ double g_sumsq[C];
__device__ float g_gain[C];
__device__ float g_b2  [C];
__device__ int   g_is64;

// ---------------- int64 vs int32 edge_index detection ----------------
__global__ void k_detect(const long long* ei, int E, int n) {
    __shared__ int s_ok;
    int cnt = E < 256 ? E : 256;   // stays within first half even if int32
    int ok = 1;
    if (threadIdx.x < cnt) {
        long long v = ei[threadIdx.x];
        if (v < 0 || v >= (long long)n) ok = 0;
    }
    int all = __syncthreads_and(ok);
    if (threadIdx.x == 0) g_is64 = all;
}

// ---------------- pack edge_index into int2 ----------------
__global__ void k_prep(const void* eiv, int E) {
    const int is64 = g_is64;
    const long long* e64 = (const long long*)eiv;
    const int*       e32 = (const int*)eiv;
    int i = blockIdx.x * blockDim.x + threadIdx.x;
    int stride = gridDim.x * blockDim.x;
    for (; i < E; i += stride) {
        int s, d;
        if (is64) { s = (int)e64[i]; d = (int)e64[E + i]; }
        else      { s = e32[i];      d = e32[E + i]; }
        g_edge[i] = make_int2(s, d);
    }
}

// ---------------- fold Wa1 into W_dst / W_src / Wp / bp ----------------
__global__ void k_fold(const float* Wsrc, const float* Wdst, const float* Wp,
                       const float* bp, const float* Wa1, const float* ba1) {
    int t = threadIdx.x;
    if (t < C * C) {
        int c = t >> 5, m = t & 31;
        float sd = 0.f, ss = 0.f;
        #pragma unroll
        for (int k = 0; k < C; k++) {
            float a = Wa1[c * C + k];
            sd = fmaf(a, Wdst[k * C + m], sd);
            ss = fmaf(a, Wsrc[k * C + m], ss);
        }
        g_Wcd[t] = sd;
        g_Wcs[t] = ss;
    }
    if (t < C * 3) {
        int c = t / 3, j = t % 3;
        float s = 0.f;
        #pragma unroll
        for (int k = 0; k < C; k++) s = fmaf(Wa1[c * C + k], Wp[k * 3 + j], s);
        g_Wp2[t] = s;
    }
    if (t < C) {
        float s = 0.f;
        #pragma unroll
        for (int k = 0; k < C; k++) s = fmaf(Wa1[t * C + k], bp[k], s);
        g_c0[t] = s + ba1[t];
        g_sum[t] = 0.0;
        g_sumsq[t] = 0.0;
    }
}

// ---------------- zero accumulators ----------------
__global__ void k_zero(int n) {
    int i = blockIdx.x * blockDim.x + threadIdx.x;
    int stride = gridDim.x * blockDim.x;
    int tot = n * C;
    for (; i < tot; i += stride) { g_den[i] = 0.f; g_acc[i] = 0.f; }
}

// ---------------- node projections: Hd, Hs, Vs, Pd ----------------
__global__ __launch_bounds__(256) void k_node(const float* x, const float* pos,
                                              const float* Wval, const float* Wp,
                                              const float* bp, int n) {
    __shared__ float sd[C * 33], ss[C * 33], sv[C * 33];
    for (int t = threadIdx.x; t < C * C; t += blockDim.x) {
        int c = t >> 5, k = t & 31;
        sd[c * 33 + k] = g_Wcd[t];
        ss[c * 33 + k] = g_Wcs[t];
        sv[c * 33 + k] = Wval[t];
    }
    __syncthreads();
    const int lane = threadIdx.x & 31;
    const int warp = (blockIdx.x * blockDim.x + threadIdx.x) >> 5;
    const int nw   = (gridDim.x * blockDim.x) >> 5;
    const float w20 = g_Wp2[lane * 3 + 0];
    const float w21 = g_Wp2[lane * 3 + 1];
    const float w22 = g_Wp2[lane * 3 + 2];
    const float wp0 = Wp[lane * 3 + 0];
    const float wp1 = Wp[lane * 3 + 1];
    const float wp2 = Wp[lane * 3 + 2];
    const float bpv = bp[lane];
    for (int nd = warp; nd < n; nd += nw) {
        float xv = x[nd * C + lane];
        float p0 = pos[nd * 3 + 0];
        float p1 = pos[nd * 3 + 1];
        float p2 = pos[nd * 3 + 2];
        float ad = 0.f, as_ = 0.f, av = 0.f;
        #pragma unroll
        for (int k = 0; k < C; k++) {
            float xk = __shfl_sync(FULLMASK, xv, k);
            ad  = fmaf(sd[lane * 33 + k], xk, ad);
            as_ = fmaf(ss[lane * 33 + k], xk, as_);
            av  = fmaf(sv[lane * 33 + k], xk, av);
        }
        float P  = fmaf(wp0, p0, fmaf(wp1, p1, wp2 * p2));
        float P2 = fmaf(w20, p0, fmaf(w21, p1, w22 * p2));
        g_Hd[nd * C + lane] = ad + P2;
        g_Hs[nd * C + lane] = as_ + P2;
        g_Vs[nd * C + lane] = av - P;
        g_Pd[nd * C + lane] = P + bpv;
    }
}

// ---------------- pass 1 over edges: BN statistics of h ----------------
#define U 4
__global__ __launch_bounds__(256) void k_stats(int E) {
    const int lane = threadIdx.x & 31;
    const int warp = (blockIdx.x * blockDim.x + threadIdx.x) >> 5;
    const int nw   = (gridDim.x * blockDim.x) >> 5;
    const float c0v = g_c0[lane];
    float sum = 0.f, sq = 0.f;
    for (int base = warp * 32; base < E; base += nw * 32) {
        int cnt = E - base; if (cnt > 32) cnt = 32;
        int2 ei = make_int2(0, 0);
        if (lane < cnt) ei = g_edge[base + lane];
        for (int j = 0; j < 32; j += U) {
            if (j >= cnt) break;
            float fhd[U], fhs[U];
            #pragma unroll
            for (int u = 0; u < U; u++) {
                int jj = j + u;
                int s = __shfl_sync(FULLMASK, ei.x, jj & 31);
                int d = __shfl_sync(FULLMASK, ei.y, jj & 31);
                if (jj < cnt) {
                    fhd[u] = g_Hd[d * C + lane];
                    fhs[u] = g_Hs[s * C + lane];
                } else { fhd[u] = 0.f; fhs[u] = 0.f; }
            }
            #pragma unroll
            for (int u = 0; u < U; u++) {
                if (j + u < cnt) {
                    float h = fhd[u] - fhs[u] + c0v;
                    sum += h;
                    sq = fmaf(h, h, sq);
                }
            }
        }
    }
    atomicAdd(&g_sum[lane],   (double)sum);
    atomicAdd(&g_sumsq[lane], (double)sq);
}

// ---------------- finalize BN affine params ----------------
__global__ void k_bn(const float* gamma, const float* beta, int E) {
    int c = threadIdx.x;
    if (c < C) {
        double mu  = g_sum[c]   / (double)E;
        double var = g_sumsq[c] / (double)E - mu * mu;
        float g = gamma[c] * rsqrtf((float)var + 1e-5f);
        g_gain[c] = g;
        g_b2[c]   = beta[c] - (float)mu * g;
    }
}

// ---------------- fused pass 2: logits -> ex -> scatter den & ex*Vs ----------------
__global__ __launch_bounds__(256) void k_edge(const float* Wa2, const float* ba2,
                                              int E) {
    const int lane = threadIdx.x & 31;
    const int warp = (blockIdx.x * blockDim.x + threadIdx.x) >> 5;
    const int nw   = (gridDim.x * blockDim.x) >> 5;
    float wa[C];
    #pragma unroll
    for (int k = 0; k < C; k++) wa[k] = Wa2[lane * C + k];
    const float c0v = g_c0[lane];
    const float gv  = g_gain[lane];
    const float bv  = g_b2[lane];
    const float bav = ba2[lane];
    for (int base = warp * 32; base < E; base += nw * 32) {
        int cnt = E - base; if (cnt > 32) cnt = 32;
        int2 ei = make_int2(0, 0);
        if (lane < cnt) ei = g_edge[base + lane];
        for (int j = 0; j < 32; j += U) {
            if (j >= cnt) break;
            int dj[U];
            float fhd[U], fhs[U], fvs[U];
            #pragma unroll
            for (int u = 0; u < U; u++) {
                int jj = j + u;
                int s = __shfl_sync(FULLMASK, ei.x, jj & 31);
                int d = __shfl_sync(FULLMASK, ei.y, jj & 31);
                dj[u] = d;
                if (jj < cnt) {
                    fhd[u] = g_Hd[d * C + lane];
                    fhs[u] = g_Hs[s * C + lane];
                    fvs[u] = g_Vs[s * C + lane];
                } else { fhd[u] = 0.f; fhs[u] = 0.f; fvs[u] = 0.f; }
            }
            #pragma unroll
            for (int u = 0; u < U; u++) {
                if (j + u < cnt) {   // warp-uniform
                    float h  = fhd[u] - fhs[u] + c0v;
                    float hn = fmaxf(fmaf(h, gv, bv), 0.f);   // BN + ReLU
                    float lg = bav;
                    #pragma unroll
                    for (int k = 0; k < C; k++)
                        lg = fmaf(wa[k], __shfl_sync(FULLMASK, hn, k), lg);
                    float ex = __expf(lg);                    // max-free softmax
                    atomicAdd(&g_den[dj[u] * C + lane], ex);
                    atomicAdd(&g_acc[dj[u] * C + lane], ex * fvs[u]);
                }
            }
        }
    }
}

// ---------------- final: out = [(acc + Pd*den)/(den+eps)] @ Wu^T + bu + x ----------
__global__ __launch_bounds__(256) void k_out(const float* x, const float* Wu,
                                             const float* bu, float* out, int n) {
    const int lane = threadIdx.x & 31;
    const int warp = (blockIdx.x * blockDim.x + threadIdx.x) >> 5;
    const int nw   = (gridDim.x * blockDim.x) >> 5;
    float wr[C];
    #pragma unroll
    for (int k = 0; k < C; k++) wr[k] = Wu[lane * C + k];
    const float buv = bu[lane];
    for (int nd = warp; nd < n; nd += nw) {
        float den = g_den[nd * C + lane];
        float acc = g_acc[nd * C + lane];
        float pd  = g_Pd [nd * C + lane];
        float a = (acc + pd * den) / (den + 1e-16f);
        float s = buv + x[nd * C + lane];
        #pragma unroll
        for (int k = 0; k < C; k++)
            s = fmaf(wr[k], __shfl_sync(FULLMASK, a, k), s);
        out[nd * C + lane] = s;
    }
}

// ---------------- launch ----------------
extern "C" void kernel_launch(void* const* d_in, const int* in_sizes, int n_in,
                              void* d_out, int out_size) {
    const float* x     = (const float*)d_in[0];
    const float* pos   = (const float*)d_in[1];
    const void*  ei    = d_in[2];
    const float* Wsrc  = (const float*)d_in[3];
    const float* Wdst  = (const float*)d_in[4];
    const float* Wval  = (const float*)d_in[5];
    const float* Wp    = (const float*)d_in[6];
    const float* bp    = (const float*)d_in[7];
    const float* Wa1   = (const float*)d_in[8];
    const float* ba1   = (const float*)d_in[9];
    const float* gamma = (const float*)d_in[10];
    const float* beta  = (const float*)d_in[11];
    const float* Wa2   = (const float*)d_in[12];
    const float* ba2   = (const float*)d_in[13];
    const float* Wu    = (const float*)d_in[14];
    const float* bu    = (const float*)d_in[15];
    float* out = (float*)d_out;

    int n = in_sizes[0] / C;
    int E = in_sizes[2] / 2;

    dim3 gb(1184), tb(256);

    k_detect<<<1, 256>>>((const long long*)ei, E, n);
    k_fold  <<<1, 1024>>>(Wsrc, Wdst, Wp, bp, Wa1, ba1);
    k_prep  <<<gb, tb>>>(ei, E);
    k_zero  <<<gb, tb>>>(n);
    k_node  <<<gb, tb>>>(x, pos, Wval, Wp, bp, n);
    k_stats <<<gb, tb>>>(E);
    k_bn    <<<1, 32>>>(gamma, beta, E);
    k_edge  <<<gb, tb>>>(Wa2, ba2, E);
    k_out   <<<gb, tb>>>(x, Wu, bu, out, n);
}

// round 3
// speedup vs baseline: 1.9296x; 1.1803x over previous
#include <cuda_runtime.h>

#define C 32
#define NMAX 100000
#define EMAX 1600000
#define FULLMASK 0xffffffffu
#define WPB 8          // warps per block (256 threads)

// ---------------- device scratch ----------------
__device__ float g_Hd [NMAX * C];      // (Wa1 Wdst)x + (Wa1 Wp)pos
__device__ float g_Hs [NMAX * C];      // (Wa1 Wsrc)x + (Wa1 Wp)pos
__device__ float g_Vs [NMAX * C];      // Wval x - Wp pos
__device__ float g_Pd [NMAX * C];      // Wp pos + bp
__device__ float g_da [NMAX * 64];     // [node][0:32]=den, [32:64]=acc
__device__ int2  g_edge[EMAX];         // packed (src,dst) int32
__device__ float g_Wcd[C * C];         // Wa1 @ W_dst
__device__ float g_Wcs[C * C];         // Wa1 @ W_src
__device__ float g_Wp2[C * 3];         // Wa1 @ Wp
__device__ float g_c0 [C];             // Wa1 @ bp + ba1
__device__ double g_sum  [C];
__device__ double g_sumsq[C];
__device__ float g_gain[C];
__device__ float g_b2  [C];
__device__ int   g_is64;

// ---------------- detect int64/int32 + fold Wa1 into upstream params ----------
__global__ void k_detectfold(const long long* ei, int E, int n,
                             const float* Wsrc, const float* Wdst, const float* Wp,
                             const float* bp, const float* Wa1, const float* ba1) {
    int t = threadIdx.x;
    // detect: int32 data read as int64 is astronomically out of range
    int cnt = E < 256 ? E : 256;
    int ok = 1;
    if (t < cnt) {
        long long v = ei[t];
        if (v < 0 || v >= (long long)n) ok = 0;
    }
    int all = __syncthreads_and(ok);
    if (t == 0) g_is64 = all;
    // fold
    if (t < C * C) {
        int c = t >> 5, m = t & 31;
        float sd = 0.f, ss = 0.f;
        #pragma unroll
        for (int k = 0; k < C; k++) {
            float a = Wa1[c * C + k];
            sd = fmaf(a, Wdst[k * C + m], sd);
            ss = fmaf(a, Wsrc[k * C + m], ss);
        }
        g_Wcd[t] = sd;
        g_Wcs[t] = ss;
    }
    if (t < C * 3) {
        int c = t / 3, j = t % 3;
        float s = 0.f;
        #pragma unroll
        for (int k = 0; k < C; k++) s = fmaf(Wa1[c * C + k], Wp[k * 3 + j], s);
        g_Wp2[t] = s;
    }
    if (t < C) {
        float s = 0.f;
        #pragma unroll
        for (int k = 0; k < C; k++) s = fmaf(Wa1[t * C + k], bp[k], s);
        g_c0[t] = s + ba1[t];
        g_sum[t] = 0.0;
        g_sumsq[t] = 0.0;
    }
}

// ---------------- zero accumulators ----------------
__global__ void k_zero(int n) {
    int i = blockIdx.x * blockDim.x + threadIdx.x;
    int stride = gridDim.x * blockDim.x;
    int tot = n * 64;
    for (; i < tot; i += stride) g_da[i] = 0.f;
}

// ---------------- node projections: Hd, Hs, Vs, Pd (4 nodes / warp iter) ------
#define NU 4
__global__ __launch_bounds__(256) void k_node(const float* x, const float* pos,
                                              const float* Wval, const float* Wp,
                                              const float* bp, int n) {
    __shared__ float sd[C * 33], ss[C * 33], sv[C * 33];
    for (int t = threadIdx.x; t < C * C; t += blockDim.x) {
        int c = t >> 5, k = t & 31;
        sd[c * 33 + k] = g_Wcd[t];
        ss[c * 33 + k] = g_Wcs[t];
        sv[c * 33 + k] = Wval[t];
    }
    __syncthreads();
    const int lane = threadIdx.x & 31;
    const int warp = (blockIdx.x * blockDim.x + threadIdx.x) >> 5;
    const int nw   = (gridDim.x * blockDim.x) >> 5;
    const float w20 = g_Wp2[lane * 3 + 0];
    const float w21 = g_Wp2[lane * 3 + 1];
    const float w22 = g_Wp2[lane * 3 + 2];
    const float wp0 = Wp[lane * 3 + 0];
    const float wp1 = Wp[lane * 3 + 1];
    const float wp2 = Wp[lane * 3 + 2];
    const float bpv = bp[lane];
    for (int nd0 = warp * NU; nd0 < n; nd0 += nw * NU) {
        float xv[NU], ad[NU], as_[NU], av[NU];
        #pragma unroll
        for (int u = 0; u < NU; u++) {
            xv[u] = (nd0 + u < n) ? x[(nd0 + u) * C + lane] : 0.f;
            ad[u] = 0.f; as_[u] = 0.f; av[u] = 0.f;
        }
        #pragma unroll
        for (int k = 0; k < C; k++) {
            float wd = sd[lane * 33 + k];
            float ws = ss[lane * 33 + k];
            float wv = sv[lane * 33 + k];
            #pragma unroll
            for (int u = 0; u < NU; u++) {
                float xk = __shfl_sync(FULLMASK, xv[u], k);
                ad[u]  = fmaf(wd, xk, ad[u]);
                as_[u] = fmaf(ws, xk, as_[u]);
                av[u]  = fmaf(wv, xk, av[u]);
            }
        }
        #pragma unroll
        for (int u = 0; u < NU; u++) {
            int nd = nd0 + u;
            if (nd < n) {
                float p0 = pos[nd * 3 + 0];
                float p1 = pos[nd * 3 + 1];
                float p2 = pos[nd * 3 + 2];
                float P  = fmaf(wp0, p0, fmaf(wp1, p1, wp2 * p2));
                float P2 = fmaf(w20, p0, fmaf(w21, p1, w22 * p2));
                g_Hd[nd * C + lane] = ad[u] + P2;
                g_Hs[nd * C + lane] = as_[u] + P2;
                g_Vs[nd * C + lane] = av[u] - P;
                g_Pd[nd * C + lane] = P + bpv;
            }
        }
    }
}

// ---------- fused prep+stats: pack edges, gather, BN statistics ----------
#define US 8
__global__ __launch_bounds__(256) void k_preps(const void* eiv, int E) {
    __shared__ int2 sE[WPB][32];
    const int lane = threadIdx.x & 31;
    const int wl   = threadIdx.x >> 5;
    const int warp = (blockIdx.x * blockDim.x + threadIdx.x) >> 5;
    const int nw   = (gridDim.x * blockDim.x) >> 5;
    const int is64 = g_is64;
    const long long* e64 = (const long long*)eiv;
    const int*       e32 = (const int*)eiv;
    const float c0v = g_c0[lane];
    float s0 = 0.f, s1 = 0.f, q0 = 0.f, q1 = 0.f;
    for (int base = warp * 32; base < E; base += nw * 32) {
        int cnt = E - base; if (cnt > 32) cnt = 32;
        if (lane < cnt) {
            int s, d;
            if (is64) { s = (int)e64[base + lane]; d = (int)e64[E + base + lane]; }
            else      { s = e32[base + lane];      d = e32[E + base + lane]; }
            int2 p = make_int2(s, d);
            g_edge[base + lane] = p;
            sE[wl][lane] = p;
        }
        __syncwarp();
        for (int j = 0; j < cnt; j += US) {
            float fhd[US], fhs[US];
            #pragma unroll
            for (int u = 0; u < US; u++) {
                int jj = j + u;
                if (jj < cnt) {
                    int2 e = sE[wl][jj];               // broadcast LDS.64
                    fhd[u] = g_Hd[e.y * C + lane];
                    fhs[u] = g_Hs[e.x * C + lane];
                } else { fhd[u] = 0.f; fhs[u] = 0.f; }
            }
            #pragma unroll
            for (int u = 0; u < US; u++) {
                if (j + u < cnt) {
                    float h = fhd[u] - fhs[u] + c0v;
                    if (u & 1) { s1 += h; q1 = fmaf(h, h, q1); }
                    else       { s0 += h; q0 = fmaf(h, h, q0); }
                }
            }
        }
        __syncwarp();
    }
    atomicAdd(&g_sum[lane],   (double)(s0 + s1));
    atomicAdd(&g_sumsq[lane], (double)(q0 + q1));
}

// ---------------- finalize BN affine params ----------------
__global__ void k_bn(const float* gamma, const float* beta, int E) {
    int c = threadIdx.x;
    if (c < C) {
        double mu  = g_sum[c]   / (double)E;
        double var = g_sumsq[c] / (double)E - mu * mu;
        float g = gamma[c] * rsqrtf((float)var + 1e-5f);
        g_gain[c] = g;
        g_b2[c]   = beta[c] - (float)mu * g;
    }
}

// ------- fused edge pass: h -> BN -> ReLU -> Wa2 (smem GEMM) -> exp -> scatter -
#define U 4
__global__ __launch_bounds__(256) void k_edge(const float* Wa2, const float* ba2,
                                              int E) {
    __shared__ int2  sE[WPB][32];
    __shared__ float sH[WPB][U][32];
    const int lane = threadIdx.x & 31;
    const int wl   = threadIdx.x >> 5;
    const int warp = (blockIdx.x * blockDim.x + threadIdx.x) >> 5;
    const int nw   = (gridDim.x * blockDim.x) >> 5;
    float wa[C];
    #pragma unroll
    for (int k = 0; k < C; k++) wa[k] = Wa2[lane * C + k];
    const float c0v = g_c0[lane];
    const float gv  = g_gain[lane];
    const float bv  = g_b2[lane];
    const float bav = ba2[lane];
    for (int base = warp * 32; base < E; base += nw * 32) {
        int cnt = E - base; if (cnt > 32) cnt = 32;
        if (lane < cnt) sE[wl][lane] = g_edge[base + lane];
        __syncwarp();
        for (int j = 0; j < cnt; j += U) {
            int dj[U];
            float fvs[U];
            #pragma unroll
            for (int u = 0; u < U; u++) {
                int jj = j + u;
                if (jj < cnt) {
                    int2 e = sE[wl][jj];               // broadcast LDS.64
                    dj[u] = e.y;
                    float fhd = g_Hd[e.y * C + lane];
                    float fhs = g_Hs[e.x * C + lane];
                    fvs[u]    = g_Vs[e.x * C + lane];
                    float h  = fhd - fhs + c0v;
                    sH[wl][u][lane] = fmaxf(fmaf(h, gv, bv), 0.f);  // BN+ReLU
                } else { dj[u] = 0; fvs[u] = 0.f; sH[wl][u][lane] = 0.f; }
            }
            __syncwarp();
            #pragma unroll
            for (int u = 0; u < U; u++) {
                if (j + u < cnt) {                     // warp-uniform
                    float lg0 = bav, lg1 = 0.f;
                    #pragma unroll
                    for (int k = 0; k < C; k += 2) {   // broadcast LDS GEMM
                        lg0 = fmaf(wa[k],     sH[wl][u][k],     lg0);
                        lg1 = fmaf(wa[k + 1], sH[wl][u][k + 1], lg1);
                    }
                    float ex = __expf(lg0 + lg1);      // max-free softmax
                    atomicAdd(&g_da[dj[u] * 64 + lane],      ex);
                    atomicAdd(&g_da[dj[u] * 64 + 32 + lane], ex * fvs[u]);
                }
            }
            __syncwarp();
        }
    }
}

// -------- final: out = [(acc + Pd*den)/(den+eps)] @ Wu^T + bu + x --------
#define NO 4
__global__ __launch_bounds__(256) void k_out(const float* x, const float* Wu,
                                             const float* bu, float* out, int n) {
    const int lane = threadIdx.x & 31;
    const int warp = (blockIdx.x * blockDim.x + threadIdx.x) >> 5;
    const int nw   = (gridDim.x * blockDim.x) >> 5;
    float wr[C];
    #pragma unroll
    for (int k = 0; k < C; k++) wr[k] = Wu[lane * C + k];
    const float buv = bu[lane];
    for (int nd0 = warp * NO; nd0 < n; nd0 += nw * NO) {
        float a[NO], s[NO];
        #pragma unroll
        for (int u = 0; u < NO; u++) {
            int nd = nd0 + u;
            if (nd < n) {
                float den = g_da[nd * 64 + lane];
                float acc = g_da[nd * 64 + 32 + lane];
                float pd  = g_Pd[nd * C + lane];
                a[u] = (acc + pd * den) / (den + 1e-16f);
                s[u] = buv + x[nd * C + lane];
            } else { a[u] = 0.f; s[u] = 0.f; }
        }
        #pragma unroll
        for (int k = 0; k < C; k++) {
            float w = wr[k];
            #pragma unroll
            for (int u = 0; u < NO; u++) {
                float ak = __shfl_sync(FULLMASK, a[u], k);
                s[u] = fmaf(w, ak, s[u]);
            }
        }
        #pragma unroll
        for (int u = 0; u < NO; u++)
            if (nd0 + u < n) out[(nd0 + u) * C + lane] = s[u];
    }
}

// ---------------- launch ----------------
extern "C" void kernel_launch(void* const* d_in, const int* in_sizes, int n_in,
                              void* d_out, int out_size) {
    const float* x     = (const float*)d_in[0];
    const float* pos   = (const float*)d_in[1];
    const void*  ei    = d_in[2];
    const float* Wsrc  = (const float*)d_in[3];
    const float* Wdst  = (const float*)d_in[4];
    const float* Wval  = (const float*)d_in[5];
    const float* Wp    = (const float*)d_in[6];
    const float* bp    = (const float*)d_in[7];
    const float* Wa1   = (const float*)d_in[8];
    const float* ba1   = (const float*)d_in[9];
    const float* gamma = (const float*)d_in[10];
    const float* beta  = (const float*)d_in[11];
    const float* Wa2   = (const float*)d_in[12];
    const float* ba2   = (const float*)d_in[13];
    const float* Wu    = (const float*)d_in[14];
    const float* bu    = (const float*)d_in[15];
    float* out = (float*)d_out;

    int n = in_sizes[0] / C;
    int E = in_sizes[2] / 2;

    dim3 gb(1184), tb(256);

    k_detectfold<<<1, 1024>>>((const long long*)ei, E, n, Wsrc, Wdst, Wp, bp, Wa1, ba1);
    k_zero <<<gb, tb>>>(n);                       // launch idx 1
    k_node <<<gb, tb>>>(x, pos, Wval, Wp, bp, n); // 2
    k_preps<<<gb, tb>>>(ei, E);                   // 3
    k_bn   <<<1, 32>>>(gamma, beta, E);           // 4
    k_edge <<<gb, tb>>>(Wa2, ba2, E);             // 5  <- ncu -s 5 catches this
    k_out  <<<gb, tb>>>(x, Wu, bu, out, n);       // 6
}

// round 4
// speedup vs baseline: 1.9553x; 1.0133x over previous
#include <cuda_runtime.h>

#define C 32
#define NMAX 100000
#define EMAX 1600000
#define FULLMASK 0xffffffffu
#define WPB 8          // warps per block (256 threads)

// ---------------- device scratch ----------------
__device__ float g_Hd [NMAX * C];      // (Wa1 Wdst)x + (Wa1 Wp)pos
__device__ float g_Hs [NMAX * C];      // (Wa1 Wsrc)x + (Wa1 Wp)pos
__device__ float g_Vs [NMAX * C];      // Wval x - Wp pos
__device__ float g_Pd [NMAX * C];      // Wp pos + bp
__device__ float g_da [NMAX * 64];     // [node][0:32]=den, [32:64]=acc
__device__ int2  g_edge[EMAX];         // packed (src*C, dst*C) element offsets
__device__ float g_Wcd[C * C];         // Wa1 @ W_dst
__device__ float g_Wcs[C * C];         // Wa1 @ W_src
__device__ float g_Wp2[C * 3];         // Wa1 @ Wp
__device__ float g_c0 [C];             // Wa1 @ bp + ba1
__device__ double g_sum  [C];
__device__ double g_sumsq[C];
__device__ int   g_is64;

// -------- detect int64/int32 + fold Wa1 into upstream params + zero sums ------
__global__ void k_detectfold(const long long* ei, int E, int n,
                             const float* Wsrc, const float* Wdst, const float* Wp,
                             const float* bp, const float* Wa1, const float* ba1) {
    int t = threadIdx.x;
    int cnt = E < 256 ? E : 256;
    int ok = 1;
    if (t < cnt) {
        long long v = ei[t];
        if (v < 0 || v >= (long long)n) ok = 0;   // int32 read as int64 -> OOR
    }
    int all = __syncthreads_and(ok);
    if (t == 0) g_is64 = all;
    if (t < C * C) {
        int c = t >> 5, m = t & 31;
        float sd = 0.f, ss = 0.f;
        #pragma unroll
        for (int k = 0; k < C; k++) {
            float a = Wa1[c * C + k];
            sd = fmaf(a, Wdst[k * C + m], sd);
            ss = fmaf(a, Wsrc[k * C + m], ss);
        }
        g_Wcd[t] = sd;
        g_Wcs[t] = ss;
    }
    if (t < C * 3) {
        int c = t / 3, j = t % 3;
        float s = 0.f;
        #pragma unroll
        for (int k = 0; k < C; k++) s = fmaf(Wa1[c * C + k], Wp[k * 3 + j], s);
        g_Wp2[t] = s;
    }
    if (t < C) {
        float s = 0.f;
        #pragma unroll
        for (int k = 0; k < C; k++) s = fmaf(Wa1[t * C + k], bp[k], s);
        g_c0[t] = s + ba1[t];
        g_sum[t] = 0.0;
        g_sumsq[t] = 0.0;
    }
}

// -------- node projections Hd, Hs, Vs, Pd (4 nodes / warp iter) + zero g_da ---
#define NU 4
__global__ __launch_bounds__(256) void k_node(const float* x, const float* pos,
                                              const float* Wval, const float* Wp,
                                              const float* bp, int n) {
    __shared__ float sd[C * 33], ss[C * 33], sv[C * 33];
    for (int t = threadIdx.x; t < C * C; t += blockDim.x) {
        int c = t >> 5, k = t & 31;
        sd[c * 33 + k] = g_Wcd[t];
        ss[c * 33 + k] = g_Wcs[t];
        sv[c * 33 + k] = Wval[t];
    }
    __syncthreads();
    const int lane = threadIdx.x & 31;
    const int warp = (blockIdx.x * blockDim.x + threadIdx.x) >> 5;
    const int nw   = (gridDim.x * blockDim.x) >> 5;
    const float w20 = g_Wp2[lane * 3 + 0];
    const float w21 = g_Wp2[lane * 3 + 1];
    const float w22 = g_Wp2[lane * 3 + 2];
    const float wp0 = Wp[lane * 3 + 0];
    const float wp1 = Wp[lane * 3 + 1];
    const float wp2 = Wp[lane * 3 + 2];
    const float bpv = bp[lane];
    for (int nd0 = warp * NU; nd0 < n; nd0 += nw * NU) {
        float xv[NU], ad[NU], as_[NU], av[NU];
        #pragma unroll
        for (int u = 0; u < NU; u++) {
            xv[u] = (nd0 + u < n) ? x[(nd0 + u) * C + lane] : 0.f;
            ad[u] = 0.f; as_[u] = 0.f; av[u] = 0.f;
        }
        #pragma unroll
        for (int k = 0; k < C; k++) {
            float wd = sd[lane * 33 + k];
            float ws = ss[lane * 33 + k];
            float wv = sv[lane * 33 + k];
            #pragma unroll
            for (int u = 0; u < NU; u++) {
                float xk = __shfl_sync(FULLMASK, xv[u], k);
                ad[u]  = fmaf(wd, xk, ad[u]);
                as_[u] = fmaf(ws, xk, as_[u]);
                av[u]  = fmaf(wv, xk, av[u]);
            }
        }
        #pragma unroll
        for (int u = 0; u < NU; u++) {
            int nd = nd0 + u;
            if (nd < n) {
                float p0 = pos[nd * 3 + 0];
                float p1 = pos[nd * 3 + 1];
                float p2 = pos[nd * 3 + 2];
                float P  = fmaf(wp0, p0, fmaf(wp1, p1, wp2 * p2));
                float P2 = fmaf(w20, p0, fmaf(w21, p1, w22 * p2));
                g_Hd[nd * C + lane] = ad[u] + P2;
                g_Hs[nd * C + lane] = as_[u] + P2;
                g_Vs[nd * C + lane] = av[u] - P;
                g_Pd[nd * C + lane] = P + bpv;
                g_da[nd * 64 + lane]      = 0.f;   // zero den
                g_da[nd * 64 + 32 + lane] = 0.f;   // zero acc
            }
        }
    }
}

// ---------- fused prep+stats: pack scaled offsets, gather, BN stats ----------
#define US 16
__global__ __launch_bounds__(256) void k_preps(const void* eiv, int E) {
    __shared__ int2 sE[WPB][32];
    const int lane = threadIdx.x & 31;
    const int wl   = threadIdx.x >> 5;
    const int warp = (blockIdx.x * blockDim.x + threadIdx.x) >> 5;
    const int nw   = (gridDim.x * blockDim.x) >> 5;
    const int is64 = g_is64;
    const long long* e64 = (const long long*)eiv;
    const int*       e32 = (const int*)eiv;
    const float c0v = g_c0[lane];
    float s0 = 0.f, s1 = 0.f, q0 = 0.f, q1 = 0.f;
    for (int base = warp * 32; base < E; base += nw * 32) {
        int cnt = E - base; if (cnt > 32) cnt = 32;
        if (lane < cnt) {
            int s, d;
            if (is64) { s = (int)e64[base + lane]; d = (int)e64[E + base + lane]; }
            else      { s = e32[base + lane];      d = e32[E + base + lane]; }
            int2 p = make_int2(s * C, d * C);      // pre-scaled element offsets
            g_edge[base + lane] = p;
            sE[wl][lane] = p;
        }
        __syncwarp();
        for (int j = 0; j < cnt; j += US) {
            float fhd[US], fhs[US];
            #pragma unroll
            for (int u = 0; u < US; u++) {
                int jj = j + u;
                if (jj < cnt) {
                    int2 e = sE[wl][jj];           // broadcast LDS.64
                    fhd[u] = g_Hd[e.y + lane];
                    fhs[u] = g_Hs[e.x + lane];
                } else { fhd[u] = 0.f; fhs[u] = 0.f; }
            }
            #pragma unroll
            for (int u = 0; u < US; u++) {
                if (j + u < cnt) {
                    float h = fhd[u] - fhs[u] + c0v;
                    if (u & 1) { s1 += h; q1 = fmaf(h, h, q1); }
                    else       { s0 += h; q0 = fmaf(h, h, q0); }
                }
            }
        }
        __syncwarp();
    }
    atomicAdd(&g_sum[lane],   (double)(s0 + s1));
    atomicAdd(&g_sumsq[lane], (double)(q0 + q1));
}

// ------- fused edge pass: BN params -> h -> BN/ReLU -> Wa2 -> exp -> scatter --
#define U 4
__global__ __launch_bounds__(256) void k_edge(const float* Wa2, const float* ba2,
                                              const float* gamma, const float* beta,
                                              int E) {
    __shared__ int2   sE[WPB][32];
    __shared__ float4 sH4[WPB][U][8];              // hn, 16B-aligned for LDS.128
    __shared__ float  sgain[C], sb2[C];
    // per-block BN finalize (replaces k_bn launch)
    if (threadIdx.x < C) {
        int c = threadIdx.x;
        double mu  = g_sum[c]   / (double)E;
        double var = g_sumsq[c] / (double)E - mu * mu;
        float g = gamma[c] * rsqrtf((float)var + 1e-5f);
        sgain[c] = g;
        sb2[c]   = beta[c] - (float)mu * g;
    }
    __syncthreads();
    const int lane = threadIdx.x & 31;
    const int wl   = threadIdx.x >> 5;
    const int warp = (blockIdx.x * blockDim.x + threadIdx.x) >> 5;
    const int nw   = (gridDim.x * blockDim.x) >> 5;
    float wa[C];
    #pragma unroll
    for (int k = 0; k < C; k++) wa[k] = Wa2[lane * C + k];
    const float c0v = g_c0[lane];
    const float gv  = sgain[lane];
    const float bv  = sb2[lane];
    const float bav = ba2[lane];
    for (int base = warp * 32; base < E; base += nw * 32) {
        int cnt = E - base; if (cnt > 32) cnt = 32;
        if (lane < cnt) sE[wl][lane] = g_edge[base + lane];
        __syncwarp();
        for (int j = 0; j < cnt; j += U) {
            int doff[U];
            float fvs[U];
            #pragma unroll
            for (int u = 0; u < U; u++) {
                int jj = j + u;
                if (jj < cnt) {
                    int2 e = sE[wl][jj];           // broadcast LDS.64
                    doff[u] = e.y;
                    float fhd = g_Hd[e.y + lane];
                    float fhs = g_Hs[e.x + lane];
                    fvs[u]    = g_Vs[e.x + lane];
                    float h = fhd - fhs + c0v;
                    ((float*)&sH4[wl][u])[lane] = fmaxf(fmaf(h, gv, bv), 0.f);
                } else { doff[u] = 0; fvs[u] = 0.f; ((float*)&sH4[wl][u])[lane] = 0.f; }
            }
            __syncwarp();
            #pragma unroll
            for (int u = 0; u < U; u++) {
                if (j + u < cnt) {                 // warp-uniform
                    float lg0 = bav, lg1 = 0.f;
                    #pragma unroll
                    for (int k4 = 0; k4 < 8; k4++) {
                        float4 hv = sH4[wl][u][k4];   // broadcast LDS.128
                        lg0 = fmaf(wa[k4 * 4 + 0], hv.x, lg0);
                        lg1 = fmaf(wa[k4 * 4 + 1], hv.y, lg1);
                        lg0 = fmaf(wa[k4 * 4 + 2], hv.z, lg0);
                        lg1 = fmaf(wa[k4 * 4 + 3], hv.w, lg1);
                    }
                    float ex = __expf(lg0 + lg1);     // max-free softmax
                    atomicAdd(&g_da[doff[u] * 2 + lane],      ex);
                    atomicAdd(&g_da[doff[u] * 2 + 32 + lane], ex * fvs[u]);
                }
            }
            __syncwarp();
        }
    }
}

// -------- final: out = [(acc + Pd*den)/(den+eps)] @ Wu^T + bu + x --------
#define NO 4
__global__ __launch_bounds__(256) void k_out(const float* x, const float* Wu,
                                             const float* bu, float* out, int n) {
    const int lane = threadIdx.x & 31;
    const int warp = (blockIdx.x * blockDim.x + threadIdx.x) >> 5;
    const int nw   = (gridDim.x * blockDim.x) >> 5;
    float wr[C];
    #pragma unroll
    for (int k = 0; k < C; k++) wr[k] = Wu[lane * C + k];
    const float buv = bu[lane];
    for (int nd0 = warp * NO; nd0 < n; nd0 += nw * NO) {
        float a[NO], s[NO];
        #pragma unroll
        for (int u = 0; u < NO; u++) {
            int nd = nd0 + u;
            if (nd < n) {
                float den = g_da[nd * 64 + lane];
                float acc = g_da[nd * 64 + 32 + lane];
                float pd  = g_Pd[nd * C + lane];
                a[u] = (acc + pd * den) / (den + 1e-16f);
                s[u] = buv + x[nd * C + lane];
            } else { a[u] = 0.f; s[u] = 0.f; }
        }
        #pragma unroll
        for (int k = 0; k < C; k++) {
            float w = wr[k];
            #pragma unroll
            for (int u = 0; u < NO; u++) {
                float ak = __shfl_sync(FULLMASK, a[u], k);
                s[u] = fmaf(w, ak, s[u]);
            }
        }
        #pragma unroll
        for (int u = 0; u < NO; u++)
            if (nd0 + u < n) out[(nd0 + u) * C + lane] = s[u];
    }
}

// ---------------- launch ----------------
extern "C" void kernel_launch(void* const* d_in, const int* in_sizes, int n_in,
                              void* d_out, int out_size) {
    const float* x     = (const float*)d_in[0];
    const float* pos   = (const float*)d_in[1];
    const void*  ei    = d_in[2];
    const float* Wsrc  = (const float*)d_in[3];
    const float* Wdst  = (const float*)d_in[4];
    const float* Wval  = (const float*)d_in[5];
    const float* Wp    = (const float*)d_in[6];
    const float* bp    = (const float*)d_in[7];
    const float* Wa1   = (const float*)d_in[8];
    const float* ba1   = (const float*)d_in[9];
    const float* gamma = (const float*)d_in[10];
    const float* beta  = (const float*)d_in[11];
    const float* Wa2   = (const float*)d_in[12];
    const float* ba2   = (const float*)d_in[13];
    const float* Wu    = (const float*)d_in[14];
    const float* bu    = (const float*)d_in[15];
    float* out = (float*)d_out;

    int n = in_sizes[0] / C;
    int E = in_sizes[2] / 2;

    dim3 gb(1184), tb(256);

    k_detectfold<<<1, 1024>>>((const long long*)ei, E, n, Wsrc, Wdst, Wp, bp, Wa1, ba1); // 0
    k_node <<<gb, tb>>>(x, pos, Wval, Wp, bp, n);          // 1 (also zeroes g_da)
    k_preps<<<gb, tb>>>(ei, E);                            // 2
    k_edge <<<gb, tb>>>(Wa2, ba2, gamma, beta, E);         // 3  <- profiled slot
    k_out  <<<gb, tb>>>(x, Wu, bu, out, n);                // 4
}

// round 5
// speedup vs baseline: 2.0660x; 1.0566x over previous
#include <cuda_runtime.h>

#define C 32
#define NMAX 100000
#define EMAX 1600000
#define FULLMASK 0xffffffffu
#define WPB 8          // warps per block (256 threads)

typedef unsigned long long ull;

__device__ __forceinline__ ull pack2(float lo, float hi) {
    ull r; asm("mov.b64 %0, {%1, %2};" : "=l"(r) : "f"(lo), "f"(hi)); return r;
}
__device__ __forceinline__ void unpack2(float& lo, float& hi, ull v) {
    asm("mov.b64 {%0, %1}, %2;" : "=f"(lo), "=f"(hi) : "l"(v));
}
__device__ __forceinline__ ull fma2(ull a, ull b, ull c) {
    ull d; asm("fma.rn.f32x2 %0, %1, %2, %3;" : "=l"(d) : "l"(a), "l"(b), "l"(c)); return d;
}
__device__ __forceinline__ ull add2(ull a, ull b) {
    ull d; asm("add.rn.f32x2 %0, %1, %2;" : "=l"(d) : "l"(a), "l"(b)); return d;
}

// ---------------- device scratch ----------------
__device__ float g_Hd [NMAX * C];      // (Wa1 Wdst)x + (Wa1 Wp)pos
__device__ float g_Hs [NMAX * C];      // (Wa1 Wsrc)x + (Wa1 Wp)pos
__device__ float g_Vs [NMAX * C];      // Wval x - Wp pos
__device__ float g_Pd [NMAX * C];      // Wp pos + bp
__device__ float g_da [NMAX * 64];     // [node][0:32]=den, [32:64]=acc
__device__ int2  g_edge[EMAX];         // packed (src*C, dst*C) element offsets
__device__ float g_Wcd[C * C];         // Wa1 @ W_dst
__device__ float g_Wcs[C * C];         // Wa1 @ W_src
__device__ float g_Wp2[C * 3];         // Wa1 @ Wp
__device__ float g_c0 [C];             // Wa1 @ bp + ba1
__device__ double g_sum  [C];
__device__ double g_sumsq[C];
__device__ int   g_is64;

// -------- detect int64/int32 + fold Wa1 into upstream params + zero sums ------
__global__ void k_detectfold(const long long* ei, int E, int n,
                             const float* Wsrc, const float* Wdst, const float* Wp,
                             const float* bp, const float* Wa1, const float* ba1) {
    int t = threadIdx.x;
    int cnt = E < 256 ? E : 256;
    int ok = 1;
    if (t < cnt) {
        long long v = ei[t];
        if (v < 0 || v >= (long long)n) ok = 0;   // int32 read as int64 -> OOR
    }
    int all = __syncthreads_and(ok);
    if (t == 0) g_is64 = all;
    if (t < C * C) {
        int c = t >> 5, m = t & 31;
        float sd = 0.f, ss = 0.f;
        #pragma unroll
        for (int k = 0; k < C; k++) {
            float a = Wa1[c * C + k];
            sd = fmaf(a, Wdst[k * C + m], sd);
            ss = fmaf(a, Wsrc[k * C + m], ss);
        }
        g_Wcd[t] = sd;
        g_Wcs[t] = ss;
    }
    if (t < C * 3) {
        int c = t / 3, j = t % 3;
        float s = 0.f;
        #pragma unroll
        for (int k = 0; k < C; k++) s = fmaf(Wa1[c * C + k], Wp[k * 3 + j], s);
        g_Wp2[t] = s;
    }
    if (t < C) {
        float s = 0.f;
        #pragma unroll
        for (int k = 0; k < C; k++) s = fmaf(Wa1[t * C + k], bp[k], s);
        g_c0[t] = s + ba1[t];
        g_sum[t] = 0.0;
        g_sumsq[t] = 0.0;
    }
}

// -------- node projections Hd, Hs, Vs, Pd (4 nodes / warp iter) + zero g_da ---
#define NU 4
__global__ __launch_bounds__(256) void k_node(const float* x, const float* pos,
                                              const float* Wval, const float* Wp,
                                              const float* bp, int n) {
    __shared__ float sd[C * 33], ss[C * 33], sv[C * 33];
    for (int t = threadIdx.x; t < C * C; t += blockDim.x) {
        int c = t >> 5, k = t & 31;
        sd[c * 33 + k] = g_Wcd[t];
        ss[c * 33 + k] = g_Wcs[t];
        sv[c * 33 + k] = Wval[t];
    }
    __syncthreads();
    const int lane = threadIdx.x & 31;
    const int warp = (blockIdx.x * blockDim.x + threadIdx.x) >> 5;
    const int nw   = (gridDim.x * blockDim.x) >> 5;
    const float w20 = g_Wp2[lane * 3 + 0];
    const float w21 = g_Wp2[lane * 3 + 1];
    const float w22 = g_Wp2[lane * 3 + 2];
    const float wp0 = Wp[lane * 3 + 0];
    const float wp1 = Wp[lane * 3 + 1];
    const float wp2 = Wp[lane * 3 + 2];
    const float bpv = bp[lane];
    for (int nd0 = warp * NU; nd0 < n; nd0 += nw * NU) {
        float xv[NU], ad[NU], as_[NU], av[NU];
        #pragma unroll
        for (int u = 0; u < NU; u++) {
            xv[u] = (nd0 + u < n) ? x[(nd0 + u) * C + lane] : 0.f;
            ad[u] = 0.f; as_[u] = 0.f; av[u] = 0.f;
        }
        #pragma unroll
        for (int k = 0; k < C; k++) {
            float wd = sd[lane * 33 + k];
            float ws = ss[lane * 33 + k];
            float wv = sv[lane * 33 + k];
            #pragma unroll
            for (int u = 0; u < NU; u++) {
                float xk = __shfl_sync(FULLMASK, xv[u], k);
                ad[u]  = fmaf(wd, xk, ad[u]);
                as_[u] = fmaf(ws, xk, as_[u]);
                av[u]  = fmaf(wv, xk, av[u]);
            }
        }
        #pragma unroll
        for (int u = 0; u < NU; u++) {
            int nd = nd0 + u;
            if (nd < n) {
                float p0 = pos[nd * 3 + 0];
                float p1 = pos[nd * 3 + 1];
                float p2 = pos[nd * 3 + 2];
                float P  = fmaf(wp0, p0, fmaf(wp1, p1, wp2 * p2));
                float P2 = fmaf(w20, p0, fmaf(w21, p1, w22 * p2));
                g_Hd[nd * C + lane] = ad[u] + P2;
                g_Hs[nd * C + lane] = as_[u] + P2;
                g_Vs[nd * C + lane] = av[u] - P;
                g_Pd[nd * C + lane] = P + bpv;
                g_da[nd * 64 + lane]      = 0.f;   // zero den
                g_da[nd * 64 + 32 + lane] = 0.f;   // zero acc
            }
        }
    }
}

// ---------- fused prep+stats: pack scaled offsets, gather, BN stats ----------
// shfl index broadcast: no smem, no syncwarp
#define US 8
__global__ __launch_bounds__(256) void k_preps(const void* eiv, int E) {
    const int lane = threadIdx.x & 31;
    const int warp = (blockIdx.x * blockDim.x + threadIdx.x) >> 5;
    const int nw   = (gridDim.x * blockDim.x) >> 5;
    const int is64 = g_is64;
    const long long* e64 = (const long long*)eiv;
    const int*       e32 = (const int*)eiv;
    const float c0v = g_c0[lane];
    float s0 = 0.f, s1 = 0.f, q0 = 0.f, q1 = 0.f;
    for (int base = warp * 32; base < E; base += nw * 32) {
        int cnt = E - base; if (cnt > 32) cnt = 32;
        int2 p = make_int2(0, 0);
        if (lane < cnt) {
            int s, d;
            if (is64) { s = (int)e64[base + lane]; d = (int)e64[E + base + lane]; }
            else      { s = e32[base + lane];      d = e32[E + base + lane]; }
            p = make_int2(s * C, d * C);           // pre-scaled element offsets
            g_edge[base + lane] = p;
        }
        for (int j = 0; j < 32; j += US) {
            if (j >= cnt) break;
            float fhd[US], fhs[US];
            #pragma unroll
            for (int u = 0; u < US; u++) {
                int jj = j + u;
                int soff = __shfl_sync(FULLMASK, p.x, jj & 31);
                int doff = __shfl_sync(FULLMASK, p.y, jj & 31);
                if (jj < cnt) {
                    fhd[u] = g_Hd[doff + lane];
                    fhs[u] = g_Hs[soff + lane];
                } else { fhd[u] = 0.f; fhs[u] = 0.f; }
            }
            #pragma unroll
            for (int u = 0; u < US; u++) {
                if (j + u < cnt) {
                    float h = fhd[u] - fhs[u] + c0v;
                    if (u & 1) { s1 += h; q1 = fmaf(h, h, q1); }
                    else       { s0 += h; q0 = fmaf(h, h, q0); }
                }
            }
        }
    }
    atomicAdd(&g_sum[lane],   (double)(s0 + s1));
    atomicAdd(&g_sumsq[lane], (double)(q0 + q1));
}

// ------- fused edge pass: 16-edge phase tiles ------------------------------
// Phase A: batched gathers -> BN/ReLU hn -> sH, Vs -> sV (no intra-phase sync)
// Phase B: f32x2 GEMM (LDS.128 broadcast) -> exp -> 2x RED scatter
#define TEDGE 16
__global__ __launch_bounds__(256) void k_edge(const float* Wa2, const float* ba2,
                                              const float* gamma, const float* beta,
                                              int E) {
    __shared__ __align__(16) float sH[WPB][TEDGE][36];  // hn, padded rows (144B)
    __shared__ float sV[WPB][TEDGE][32];                // stashed Vs[src]
    __shared__ float sgain[C], sb2[C];
    // per-block BN finalize
    if (threadIdx.x < C) {
        int c = threadIdx.x;
        double mu  = g_sum[c]   / (double)E;
        double var = g_sumsq[c] / (double)E - mu * mu;
        float g = gamma[c] * rsqrtf((float)var + 1e-5f);
        sgain[c] = g;
        sb2[c]   = beta[c] - (float)mu * g;
    }
    __syncthreads();
    const int lane = threadIdx.x & 31;
    const int wl   = threadIdx.x >> 5;
    const int warp = (blockIdx.x * blockDim.x + threadIdx.x) >> 5;
    const int nw   = (gridDim.x * blockDim.x) >> 5;
    // Wa2 row for this lane, packed as 16 x f32x2
    ull wa2r[16];
    #pragma unroll
    for (int i = 0; i < 16; i++)
        wa2r[i] = pack2(Wa2[lane * C + 2 * i], Wa2[lane * C + 2 * i + 1]);
    const float c0v = g_c0[lane];
    const float gv  = sgain[lane];
    const float bv  = sb2[lane];
    const ull   bav2 = pack2(ba2[lane], 0.f);
    for (int base = warp * 32; base < E; base += nw * 32) {
        int cnt = E - base; if (cnt > 32) cnt = 32;
        int2 ei = make_int2(0, 0);
        if (lane < cnt) ei = g_edge[base + lane];
        #pragma unroll
        for (int half = 0; half < 2; half++) {
            const int h0 = half * TEDGE;
            int hcnt = cnt - h0; if (hcnt > TEDGE) hcnt = TEDGE;
            if (hcnt <= 0) break;
            // ---- Phase A: gathers (12 in flight per sub-batch), hn -> smem ----
            #pragma unroll
            for (int jb = 0; jb < TEDGE; jb += 4) {
                float fhd[4], fhs[4], fvs[4];
                #pragma unroll
                for (int u = 0; u < 4; u++) {
                    int e = jb + u;
                    int soff = __shfl_sync(FULLMASK, ei.x, h0 + e);
                    int doff = __shfl_sync(FULLMASK, ei.y, h0 + e);
                    if (e < hcnt) {
                        fhd[u] = g_Hd[doff + lane];
                        fhs[u] = g_Hs[soff + lane];
                        fvs[u] = g_Vs[soff + lane];
                    } else { fhd[u] = 0.f; fhs[u] = 0.f; fvs[u] = 0.f; }
                }
                #pragma unroll
                for (int u = 0; u < 4; u++) {
                    int e = jb + u;
                    float h = fhd[u] - fhs[u] + c0v;
                    sH[wl][e][lane] = fmaxf(fmaf(h, gv, bv), 0.f);  // BN+ReLU
                    sV[wl][e][lane] = fvs[u];
                }
            }
            __syncwarp();
            // ---- Phase B: f32x2 GEMM + exp + scatter ----
            #pragma unroll 4
            for (int e = 0; e < TEDGE; e++) {
                if (e >= hcnt) break;                  // warp-uniform
                int doff = __shfl_sync(FULLMASK, ei.y, h0 + e);
                const ulonglong2* hrow = (const ulonglong2*)&sH[wl][e][0];
                ull acc0 = bav2, acc1 = pack2(0.f, 0.f);
                #pragma unroll
                for (int k4 = 0; k4 < 8; k4++) {
                    ulonglong2 hv = hrow[k4];          // LDS.128 broadcast
                    acc0 = fma2(wa2r[k4 * 2],     hv.x, acc0);
                    acc1 = fma2(wa2r[k4 * 2 + 1], hv.y, acc1);
                }
                ull accs = add2(acc0, acc1);
                float lo, hi; unpack2(lo, hi, accs);
                float ex = __expf(lo + hi);            // max-free softmax
                float fvs = sV[wl][e][lane];
                int b = doff * 2 + lane;               // doff = dst*32 -> dst*64
                atomicAdd(&g_da[b],      ex);
                atomicAdd(&g_da[b + 32], ex * fvs);
            }
            __syncwarp();
        }
    }
}

// -------- final: out = [(acc + Pd*den)/(den+eps)] @ Wu^T + bu + x --------
#define NO 4
__global__ __launch_bounds__(256) void k_out(const float* x, const float* Wu,
                                             const float* bu, float* out, int n) {
    const int lane = threadIdx.x & 31;
    const int warp = (blockIdx.x * blockDim.x + threadIdx.x) >> 5;
    const int nw   = (gridDim.x * blockDim.x) >> 5;
    float wr[C];
    #pragma unroll
    for (int k = 0; k < C; k++) wr[k] = Wu[lane * C + k];
    const float buv = bu[lane];
    for (int nd0 = warp * NO; nd0 < n; nd0 += nw * NO) {
        float a[NO], s[NO];
        #pragma unroll
        for (int u = 0; u < NO; u++) {
            int nd = nd0 + u;
            if (nd < n) {
                float den = g_da[nd * 64 + lane];
                float acc = g_da[nd * 64 + 32 + lane];
                float pd  = g_Pd[nd * C + lane];
                a[u] = (acc + pd * den) / (den + 1e-16f);
                s[u] = buv + x[nd * C + lane];
            } else { a[u] = 0.f; s[u] = 0.f; }
        }
        #pragma unroll
        for (int k = 0; k < C; k++) {
            float w = wr[k];
            #pragma unroll
            for (int u = 0; u < NO; u++) {
                float ak = __shfl_sync(FULLMASK, a[u], k);
                s[u] = fmaf(w, ak, s[u]);
            }
        }
        #pragma unroll
        for (int u = 0; u < NO; u++)
            if (nd0 + u < n) out[(nd0 + u) * C + lane] = s[u];
    }
}

// ---------------- launch ----------------
extern "C" void kernel_launch(void* const* d_in, const int* in_sizes, int n_in,
                              void* d_out, int out_size) {
    const float* x     = (const float*)d_in[0];
    const float* pos   = (const float*)d_in[1];
    const void*  ei    = d_in[2];
    const float* Wsrc  = (const float*)d_in[3];
    const float* Wdst  = (const float*)d_in[4];
    const float* Wval  = (const float*)d_in[5];
    const float* Wp    = (const float*)d_in[6];
    const float* bp    = (const float*)d_in[7];
    const float* Wa1   = (const float*)d_in[8];
    const float* ba1   = (const float*)d_in[9];
    const float* gamma = (const float*)d_in[10];
    const float* beta  = (const float*)d_in[11];
    const float* Wa2   = (const float*)d_in[12];
    const float* ba2   = (const float*)d_in[13];
    const float* Wu    = (const float*)d_in[14];
    const float* bu    = (const float*)d_in[15];
    float* out = (float*)d_out;

    int n = in_sizes[0] / C;
    int E = in_sizes[2] / 2;

    dim3 gb(1184), tb(256);

    k_detectfold<<<1, 1024>>>((const long long*)ei, E, n, Wsrc, Wdst, Wp, bp, Wa1, ba1); // 0
    k_node <<<gb, tb>>>(x, pos, Wval, Wp, bp, n);          // 1 (also zeroes g_da)
    k_preps<<<gb, tb>>>(ei, E);                            // 2
    k_edge <<<gb, tb>>>(Wa2, ba2, gamma, beta, E);         // 3  <- profiled slot
    k_out  <<<gb, tb>>>(x, Wu, bu, out, n);                // 4
}

// round 6
// speedup vs baseline: 2.0664x; 1.0002x over previous
#include <cuda_runtime.h>

#define C 32
#define NMAX 100000
#define EMAX 1600000
#define FULLMASK 0xffffffffu
#define WPB 8          // warps per block (256 threads)

typedef unsigned long long ull;

__device__ __forceinline__ ull pack2(float lo, float hi) {
    ull r; asm("mov.b64 %0, {%1, %2};" : "=l"(r) : "f"(lo), "f"(hi)); return r;
}
__device__ __forceinline__ void unpack2(float& lo, float& hi, ull v) {
    asm("mov.b64 {%0, %1}, %2;" : "=f"(lo), "=f"(hi) : "l"(v));
}
__device__ __forceinline__ ull fma2(ull a, ull b, ull c) {
    ull d; asm("fma.rn.f32x2 %0, %1, %2, %3;" : "=l"(d) : "l"(a), "l"(b), "l"(c)); return d;
}
__device__ __forceinline__ ull add2(ull a, ull b) {
    ull d; asm("add.rn.f32x2 %0, %1, %2;" : "=l"(d) : "l"(a), "l"(b)); return d;
}

// ---------------- device scratch ----------------
__device__ float g_Hd [NMAX * C];      // (Wa1 Wdst)x + (Wa1 Wp)pos
__device__ float g_Hs [NMAX * C];      // (Wa1 Wsrc)x + (Wa1 Wp)pos
__device__ float g_Vs [NMAX * C];      // Wval x - Wp pos
__device__ float g_Pd [NMAX * C];      // Wp pos + bp
__device__ float g_da [NMAX * 64];     // [node][0:32]=den, [32:64]=acc
__device__ int2  g_edge[EMAX];         // packed (src*C, dst*C) element offsets
__device__ float g_h  [(long long)EMAX * C]; // per-edge pre-BN h (streamed)
__device__ float g_Wcd[C * C];         // Wa1 @ W_dst
__device__ float g_Wcs[C * C];         // Wa1 @ W_src
__device__ float g_Wp2[C * 3];         // Wa1 @ Wp
__device__ float g_c0 [C];             // Wa1 @ bp + ba1
__device__ double g_sum  [C];
__device__ double g_sumsq[C];
__device__ int   g_is64;

// -------- detect int64/int32 + fold Wa1 into upstream params + zero sums ------
__global__ void k_detectfold(const long long* ei, int E, int n,
                             const float* Wsrc, const float* Wdst, const float* Wp,
                             const float* bp, const float* Wa1, const float* ba1) {
    int t = threadIdx.x;
    int cnt = E < 256 ? E : 256;
    int ok = 1;
    if (t < cnt) {
        long long v = ei[t];
        if (v < 0 || v >= (long long)n) ok = 0;   // int32 read as int64 -> OOR
    }
    int all = __syncthreads_and(ok);
    if (t == 0) g_is64 = all;
    if (t < C * C) {
        int c = t >> 5, m = t & 31;
        float sd = 0.f, ss = 0.f;
        #pragma unroll
        for (int k = 0; k < C; k++) {
            float a = Wa1[c * C + k];
            sd = fmaf(a, Wdst[k * C + m], sd);
            ss = fmaf(a, Wsrc[k * C + m], ss);
        }
        g_Wcd[t] = sd;
        g_Wcs[t] = ss;
    }
    if (t < C * 3) {
        int c = t / 3, j = t % 3;
        float s = 0.f;
        #pragma unroll
        for (int k = 0; k < C; k++) s = fmaf(Wa1[c * C + k], Wp[k * 3 + j], s);
        g_Wp2[t] = s;
    }
    if (t < C) {
        float s = 0.f;
        #pragma unroll
        for (int k = 0; k < C; k++) s = fmaf(Wa1[t * C + k], bp[k], s);
        g_c0[t] = s + ba1[t];
        g_sum[t] = 0.0;
        g_sumsq[t] = 0.0;
    }
}

// -------- node projections Hd, Hs, Vs, Pd (4 nodes / warp iter) + zero g_da ---
#define NU 4
__global__ __launch_bounds__(256) void k_node(const float* x, const float* pos,
                                              const float* Wval, const float* Wp,
                                              const float* bp, int n) {
    __shared__ float sd[C * 33], ss[C * 33], sv[C * 33];
    for (int t = threadIdx.x; t < C * C; t += blockDim.x) {
        int c = t >> 5, k = t & 31;
        sd[c * 33 + k] = g_Wcd[t];
        ss[c * 33 + k] = g_Wcs[t];
        sv[c * 33 + k] = Wval[t];
    }
    __syncthreads();
    const int lane = threadIdx.x & 31;
    const int warp = (blockIdx.x * blockDim.x + threadIdx.x) >> 5;
    const int nw   = (gridDim.x * blockDim.x) >> 5;
    const float w20 = g_Wp2[lane * 3 + 0];
    const float w21 = g_Wp2[lane * 3 + 1];
    const float w22 = g_Wp2[lane * 3 + 2];
    const float wp0 = Wp[lane * 3 + 0];
    const float wp1 = Wp[lane * 3 + 1];
    const float wp2 = Wp[lane * 3 + 2];
    const float bpv = bp[lane];
    for (int nd0 = warp * NU; nd0 < n; nd0 += nw * NU) {
        float xv[NU], ad[NU], as_[NU], av[NU];
        #pragma unroll
        for (int u = 0; u < NU; u++) {
            xv[u] = (nd0 + u < n) ? x[(nd0 + u) * C + lane] : 0.f;
            ad[u] = 0.f; as_[u] = 0.f; av[u] = 0.f;
        }
        #pragma unroll
        for (int k = 0; k < C; k++) {
            float wd = sd[lane * 33 + k];
            float ws = ss[lane * 33 + k];
            float wv = sv[lane * 33 + k];
            #pragma unroll
            for (int u = 0; u < NU; u++) {
                float xk = __shfl_sync(FULLMASK, xv[u], k);
                ad[u]  = fmaf(wd, xk, ad[u]);
                as_[u] = fmaf(ws, xk, as_[u]);
                av[u]  = fmaf(wv, xk, av[u]);
            }
        }
        #pragma unroll
        for (int u = 0; u < NU; u++) {
            int nd = nd0 + u;
            if (nd < n) {
                float p0 = pos[nd * 3 + 0];
                float p1 = pos[nd * 3 + 1];
                float p2 = pos[nd * 3 + 2];
                float P  = fmaf(wp0, p0, fmaf(wp1, p1, wp2 * p2));
                float P2 = fmaf(w20, p0, fmaf(w21, p1, w22 * p2));
                g_Hd[nd * C + lane] = ad[u] + P2;
                g_Hs[nd * C + lane] = as_[u] + P2;
                g_Vs[nd * C + lane] = av[u] - P;
                g_Pd[nd * C + lane] = P + bpv;
                g_da[nd * 64 + lane]      = 0.f;   // zero den
                g_da[nd * 64 + 32 + lane] = 0.f;   // zero acc
            }
        }
    }
}

// ---------- fused prep+stats: pack offsets, gather, BN stats, stream h out ----
#define US 8
__global__ __launch_bounds__(256) void k_preps(const void* eiv, int E) {
    const int lane = threadIdx.x & 31;
    const int warp = (blockIdx.x * blockDim.x + threadIdx.x) >> 5;
    const int nw   = (gridDim.x * blockDim.x) >> 5;
    const int is64 = g_is64;
    const long long* e64 = (const long long*)eiv;
    const int*       e32 = (const int*)eiv;
    const float c0v = g_c0[lane];
    float s0 = 0.f, s1 = 0.f, q0 = 0.f, q1 = 0.f;
    for (int base = warp * 32; base < E; base += nw * 32) {
        int cnt = E - base; if (cnt > 32) cnt = 32;
        int2 p = make_int2(0, 0);
        if (lane < cnt) {
            int s, d;
            if (is64) { s = (int)e64[base + lane]; d = (int)e64[E + base + lane]; }
            else      { s = e32[base + lane];      d = e32[E + base + lane]; }
            p = make_int2(s * C, d * C);           // pre-scaled element offsets
            g_edge[base + lane] = p;
        }
        for (int j = 0; j < 32; j += US) {
            if (j >= cnt) break;
            float fhd[US], fhs[US];
            #pragma unroll
            for (int u = 0; u < US; u++) {
                int jj = j + u;
                int soff = __shfl_sync(FULLMASK, p.x, jj & 31);
                int doff = __shfl_sync(FULLMASK, p.y, jj & 31);
                if (jj < cnt) {
                    fhd[u] = g_Hd[doff + lane];
                    fhs[u] = g_Hs[soff + lane];
                } else { fhd[u] = 0.f; fhs[u] = 0.f; }
            }
            #pragma unroll
            for (int u = 0; u < US; u++) {
                int jj = j + u;
                if (jj < cnt) {
                    float h = fhd[u] - fhs[u] + c0v;
                    __stcs(&g_h[(long long)(base + jj) * C + lane], h); // stream h
                    if (u & 1) { s1 += h; q1 = fmaf(h, h, q1); }
                    else       { s0 += h; q0 = fmaf(h, h, q0); }
                }
            }
        }
    }
    atomicAdd(&g_sum[lane],   (double)(s0 + s1));
    atomicAdd(&g_sumsq[lane], (double)(q0 + q1));
}

// ------- fused edge pass: stream h -> BN/ReLU -> f32x2 GEMM -> exp -> scatter -
#define TEDGE 16
__global__ __launch_bounds__(256) void k_edge(const float* Wa2, const float* ba2,
                                              const float* gamma, const float* beta,
                                              int E) {
    __shared__ __align__(16) float sH[WPB][TEDGE][36];  // hn, padded rows
    __shared__ float sgain[C], sb2[C];
    // per-block BN finalize
    if (threadIdx.x < C) {
        int c = threadIdx.x;
        double mu  = g_sum[c]   / (double)E;
        double var = g_sumsq[c] / (double)E - mu * mu;
        float g = gamma[c] * rsqrtf((float)var + 1e-5f);
        sgain[c] = g;
        sb2[c]   = beta[c] - (float)mu * g;
    }
    __syncthreads();
    const int lane = threadIdx.x & 31;
    const int wl   = threadIdx.x >> 5;
    const int warp = (blockIdx.x * blockDim.x + threadIdx.x) >> 5;
    const int nw   = (gridDim.x * blockDim.x) >> 5;
    // Wa2 row for this lane, packed as 16 x f32x2
    ull wa2r[16];
    #pragma unroll
    for (int i = 0; i < 16; i++)
        wa2r[i] = pack2(Wa2[lane * C + 2 * i], Wa2[lane * C + 2 * i + 1]);
    const float gv  = sgain[lane];
    const float bv  = sb2[lane];
    const ull   bav2 = pack2(ba2[lane], 0.f);
    for (int base = warp * 32; base < E; base += nw * 32) {
        int cnt = E - base; if (cnt > 32) cnt = 32;
        int2 ei = make_int2(0, 0);
        if (lane < cnt) ei = g_edge[base + lane];
        #pragma unroll
        for (int half = 0; half < 2; half++) {
            const int h0 = half * TEDGE;
            int hcnt = cnt - h0; if (hcnt > TEDGE) hcnt = TEDGE;
            if (hcnt <= 0) break;
            // ---- Phase A: stream h (sequential), BN+ReLU, stage hn ----
            #pragma unroll
            for (int jb = 0; jb < TEDGE; jb += 4) {
                float fh[4];
                #pragma unroll
                for (int u = 0; u < 4; u++) {
                    int e = jb + u;
                    fh[u] = (e < hcnt)
                        ? __ldcs(&g_h[(long long)(base + h0 + e) * C + lane])
                        : 0.f;
                }
                #pragma unroll
                for (int u = 0; u < 4; u++)
                    sH[wl][jb + u][lane] = fmaxf(fmaf(fh[u], gv, bv), 0.f);
            }
            __syncwarp();
            // ---- Phase B: f32x2 GEMM + exp + Vs gather + scatter ----
            #pragma unroll 4
            for (int e = 0; e < TEDGE; e++) {
                if (e >= hcnt) break;                  // warp-uniform
                int soff = __shfl_sync(FULLMASK, ei.x, h0 + e);
                int doff = __shfl_sync(FULLMASK, ei.y, h0 + e);
                float fvs = g_Vs[soff + lane];         // only random gather left
                const ulonglong2* hrow = (const ulonglong2*)&sH[wl][e][0];
                ull acc0 = bav2, acc1 = pack2(0.f, 0.f);
                #pragma unroll
                for (int k4 = 0; k4 < 8; k4++) {
                    ulonglong2 hv = hrow[k4];          // LDS.128 broadcast
                    acc0 = fma2(wa2r[k4 * 2],     hv.x, acc0);
                    acc1 = fma2(wa2r[k4 * 2 + 1], hv.y, acc1);
                }
                ull accs = add2(acc0, acc1);
                float lo, hi; unpack2(lo, hi, accs);
                float ex = __expf(lo + hi);            // max-free softmax
                int b = doff * 2 + lane;               // doff = dst*32 -> dst*64
                atomicAdd(&g_da[b],      ex);
                atomicAdd(&g_da[b + 32], ex * fvs);
            }
            __syncwarp();
        }
    }
}

// -------- final: out = [(acc + Pd*den)/(den+eps)] @ Wu^T + bu + x --------
#define NO 4
__global__ __launch_bounds__(256) void k_out(const float* x, const float* Wu,
                                             const float* bu, float* out, int n) {
    const int lane = threadIdx.x & 31;
    const int warp = (blockIdx.x * blockDim.x + threadIdx.x) >> 5;
    const int nw   = (gridDim.x * blockDim.x) >> 5;
    float wr[C];
    #pragma unroll
    for (int k = 0; k < C; k++) wr[k] = Wu[lane * C + k];
    const float buv = bu[lane];
    for (int nd0 = warp * NO; nd0 < n; nd0 += nw * NO) {
        float a[NO], s[NO];
        #pragma unroll
        for (int u = 0; u < NO; u++) {
            int nd = nd0 + u;
            if (nd < n) {
                float den = g_da[nd * 64 + lane];
                float acc = g_da[nd * 64 + 32 + lane];
                float pd  = g_Pd[nd * C + lane];
                a[u] = (acc + pd * den) / (den + 1e-16f);
                s[u] = buv + x[nd * C + lane];
            } else { a[u] = 0.f; s[u] = 0.f; }
        }
        #pragma unroll
        for (int k = 0; k < C; k++) {
            float w = wr[k];
            #pragma unroll
            for (int u = 0; u < NO; u++) {
                float ak = __shfl_sync(FULLMASK, a[u], k);
                s[u] = fmaf(w, ak, s[u]);
            }
        }
        #pragma unroll
        for (int u = 0; u < NO; u++)
            if (nd0 + u < n) out[(nd0 + u) * C + lane] = s[u];
    }
}

// ---------------- launch ----------------
extern "C" void kernel_launch(void* const* d_in, const int* in_sizes, int n_in,
                              void* d_out, int out_size) {
    const float* x     = (const float*)d_in[0];
    const float* pos   = (const float*)d_in[1];
    const void*  ei    = d_in[2];
    const float* Wsrc  = (const float*)d_in[3];
    const float* Wdst  = (const float*)d_in[4];
    const float* Wval  = (const float*)d_in[5];
    const float* Wp    = (const float*)d_in[6];
    const float* bp    = (const float*)d_in[7];
    const float* Wa1   = (const float*)d_in[8];
    const float* ba1   = (const float*)d_in[9];
    const float* gamma = (const float*)d_in[10];
    const float* beta  = (const float*)d_in[11];
    const float* Wa2   = (const float*)d_in[12];
    const float* ba2   = (const float*)d_in[13];
    const float* Wu    = (const float*)d_in[14];
    const float* bu    = (const float*)d_in[15];
    float* out = (float*)d_out;

    int n = in_sizes[0] / C;
    int E = in_sizes[2] / 2;

    dim3 gb(1184), tb(256);

    k_detectfold<<<1, 1024>>>((const long long*)ei, E, n, Wsrc, Wdst, Wp, bp, Wa1, ba1); // 0
    k_node <<<gb, tb>>>(x, pos, Wval, Wp, bp, n);          // 1 (also zeroes g_da)
    k_preps<<<gb, tb>>>(ei, E);                            // 2
    k_edge <<<gb, tb>>>(Wa2, ba2, gamma, beta, E);         // 3  <- profiled slot
    k_out  <<<gb, tb>>>(x, Wu, bu, out, n);                // 4
}